// round 13
// baseline (speedup 1.0000x reference)
#include <cuda_runtime.h>

// GEMV: y = alpha * (A @ x) + beta * b
// A: [16384,16384] f32. Probe: TPB=512, 4 CTAs/SM (launch_bounds(512,4))
// -> same 2048 threads/SM occupancy as best-so-far, but only 4 concurrent
// row-streams per SM (vs 8), each a contiguous 64KB sequential stream.
// Tests whether fewer/fatter DRAM streams beat 8/SM.

#define ROWS 16384
#define COLS 16384
#define TPB  512

__global__ __launch_bounds__(TPB, 4) void gemv_kernel(
    const float* __restrict__ alpha,
    const float* __restrict__ A,
    const float* __restrict__ x,
    const float* __restrict__ beta,
    const float* __restrict__ b,
    float* __restrict__ y)
{
    const int row = blockIdx.x;
    const int tid = threadIdx.x;

    const float4* __restrict__ arow = reinterpret_cast<const float4*>(A + (size_t)row * COLS);
    const float4* __restrict__ xv   = reinterpret_cast<const float4*>(x);

    float acc = 0.0f;

    // COLS/4 = 4096 float4; 512 threads -> 8 iterations; unroll 4.
    #pragma unroll 4
    for (int i = tid; i < COLS / 4; i += TPB) {
        float4 a = __ldcs(&arow[i]);
        float4 v = __ldg(&xv[i]);
        acc = fmaf(a.x, v.x, acc);
        acc = fmaf(a.y, v.y, acc);
        acc = fmaf(a.z, v.z, acc);
        acc = fmaf(a.w, v.w, acc);
    }

    // warp reduce
    #pragma unroll
    for (int off = 16; off > 0; off >>= 1)
        acc += __shfl_xor_sync(0xFFFFFFFFu, acc, off);

    __shared__ float warp_sums[TPB / 32];
    const int lane = tid & 31;
    const int wid  = tid >> 5;
    if (lane == 0) warp_sums[wid] = acc;
    __syncthreads();

    if (wid == 0) {
        float s = (lane < TPB / 32) ? warp_sums[lane] : 0.0f;
        #pragma unroll
        for (int off = 8; off > 0; off >>= 1)
            s += __shfl_xor_sync(0xFFFFFFFFu, s, off);
        if (lane == 0)
            y[row] = alpha[0] * s + beta[0] * b[row];
    }
}

extern "C" void kernel_launch(void* const* d_in, const int* in_sizes, int n_in,
                              void* d_out, int out_size) {
    const float* alpha = (const float*)d_in[0];
    const float* A     = (const float*)d_in[1];
    const float* x     = (const float*)d_in[2];
    const float* beta  = (const float*)d_in[3];
    const float* b     = (const float*)d_in[4];
    float* y = (float*)d_out;

    gemv_kernel<<<ROWS, TPB>>>(alpha, A, x, beta, b, y);
}